// round 7
// baseline (speedup 1.0000x reference)
#include <cuda_runtime.h>
#include <math.h>
#include <stdint.h>

#define NN 100000
#define NE 1600000
#define ETOT (NE + NN)
#define HD192 192
#define D64 64
#define HD63 63
#define D21 21
#define NG 8
#define NCLS 10
#define EPSBN 1e-5f
#define SBLK 98          // scan blocks: 98 * 1024 >= NN

// ---------------- scratch (device globals; no allocs allowed) ----------------
__device__ float g_xl[(size_t)NN * HD192];
__device__ float g_xr[(size_t)NN * HD192];
__device__ float g_h[(size_t)NN * HD192];
__device__ float g_h2[(size_t)NN * D64];
__device__ int   g_counts[NN];
__device__ int   g_rowptr[NN + 1];
__device__ int   g_cursor[NN];
__device__ int   g_col[ETOT];
__device__ int   g_bsum[SBLK];
__device__ int   g_boff[SBLK];
__device__ float g_bnsum[HD192];
__device__ float g_bnsq[HD192];
__device__ float g_bnscale[HD192];
__device__ float g_bnshift[HD192];
__device__ float g_pool[NG * D64];
__device__ float g_cnt[NG];

// ---------------- small resets ----------------
__global__ void reset_small_kernel() {
    int t = threadIdx.x;
    if (t < HD192) { g_bnsum[t] = 0.f; g_bnsq[t] = 0.f; }
    if (t < NG * D64) g_pool[t] = 0.f;
    if (t < NG) g_cnt[t] = 0.f;
}

// ---------------- CSR build ----------------
__global__ void init_counts_kernel() {
    int i = blockIdx.x * blockDim.x + threadIdx.x;
    if (i < NN) g_counts[i] = 1;   // self loop
}

__global__ void hist_kernel(const int* __restrict__ dst) {
    int e = blockIdx.x * blockDim.x + threadIdx.x;
    if (e < NE) atomicAdd(&g_counts[dst[e]], 1);
}

__global__ void scan1_kernel() {
    __shared__ int ss[256];
    int t = threadIdx.x, b = blockIdx.x;
    int base = b * 1024 + t * 4;
    int s = 0;
    #pragma unroll
    for (int q = 0; q < 4; q++) { int i = base + q; if (i < NN) s += g_counts[i]; }
    ss[t] = s;
    __syncthreads();
    for (int off = 1; off < 256; off <<= 1) {
        int v = (t >= off) ? ss[t - off] : 0;
        __syncthreads();
        ss[t] += v;
        __syncthreads();
    }
    if (t == 255) g_bsum[b] = ss[255];
}

__global__ void scan2_kernel() {
    __shared__ int ss[128];
    int t = threadIdx.x;
    ss[t] = (t < SBLK) ? g_bsum[t] : 0;
    __syncthreads();
    for (int off = 1; off < 128; off <<= 1) {
        int v = (t >= off) ? ss[t - off] : 0;
        __syncthreads();
        ss[t] += v;
        __syncthreads();
    }
    if (t < SBLK) g_boff[t] = t ? ss[t - 1] : 0;
    if (t == 127) g_rowptr[NN] = ss[127];
}

__global__ void scan3_kernel() {
    __shared__ int ss[256];
    int t = threadIdx.x, b = blockIdx.x;
    int base = b * 1024 + t * 4;
    int cnt[4]; int s = 0;
    #pragma unroll
    for (int q = 0; q < 4; q++) {
        cnt[q] = (base + q < NN) ? g_counts[base + q] : 0;
        s += cnt[q];
    }
    ss[t] = s;
    __syncthreads();
    for (int off = 1; off < 256; off <<= 1) {
        int v = (t >= off) ? ss[t - off] : 0;
        __syncthreads();
        ss[t] += v;
        __syncthreads();
    }
    int pre = g_boff[b] + (t ? ss[t - 1] : 0);
    #pragma unroll
    for (int q = 0; q < 4; q++) {
        int i = base + q;
        if (i < NN) { g_rowptr[i] = pre; g_cursor[i] = pre; pre += cnt[q]; }
    }
}

__global__ void csr_fill_kernel(const int* __restrict__ src, const int* __restrict__ dst) {
    int e = blockIdx.x * blockDim.x + threadIdx.x;
    if (e >= ETOT) return;
    int s, d;
    if (e < NE) { s = src[e]; d = dst[e]; } else { s = d = e - NE; }
    int pos = atomicAdd(&g_cursor[d], 1);
    g_col[pos] = s;
}

// ---------------- TF32 tensor-core GEMM ----------------
// C[M,N] = f(A)[M,K] @ B[K,N], row stride ldC; mode 0=id, 1=relu(A), 2=BN(A)
#define SAS 136

__device__ __forceinline__ uint32_t f2tf32(float f) {
    uint32_t u;
    asm("cvt.rna.tf32.f32 %0, %1;" : "=r"(u) : "f"(f));
    return u;
}

__global__ void gemm_tf32_kernel(const float* __restrict__ A,
                                 const float* __restrict__ Bl, const float* __restrict__ Br,
                                 float* __restrict__ Cl, float* __restrict__ Cr,
                                 int M, int N, int K, int ldC, int mode) {
    extern __shared__ uint32_t smem[];
    const int K4 = K + 4;
    uint32_t* sBT = smem;                 // [64][K4]
    uint32_t* sA  = smem + 64 * K4;       // [32][SAS]

    int tid = threadIdx.x;
    const float* Bg = blockIdx.z ? Br : Bl;
    float* Cg = blockIdx.z ? Cr : Cl;
    int col0 = blockIdx.x * 64;
    int row0 = blockIdx.y * 128;

    for (int i = tid; i < K * 16; i += 256) {
        int k = i >> 4, n4 = (i & 15) * 4;
        #pragma unroll
        for (int q = 0; q < 4; q++) {
            int n = n4 + q;
            float v = (col0 + n < N) ? Bg[(size_t)k * N + col0 + n] : 0.f;
            sBT[n * K4 + k] = f2tf32(v);
        }
    }

    int lane = tid & 31, w = tid >> 5;
    int mw = (w & 3) * 32, nw = (w >> 2) * 32;
    int g = lane >> 2, c = lane & 3;

    float acc[2][4][4] = {};

    for (int k0 = 0; k0 < K; k0 += 32) {
        #pragma unroll
        for (int l = 0; l < 4; l++) {
            int i = tid + l * 256;
            int r = i >> 3, c4 = (i & 7) * 4;
            int gr = row0 + r;
            float4 v = make_float4(0.f, 0.f, 0.f, 0.f);
            if (gr < M) v = *(const float4*)&A[(size_t)gr * K + k0 + c4];
            float vv[4] = {v.x, v.y, v.z, v.w};
            #pragma unroll
            for (int q = 0; q < 4; q++) {
                float f = vv[q];
                int kc = k0 + c4 + q;
                if (mode == 1) f = fmaxf(f, 0.f);
                else if (mode == 2) f = f * g_bnscale[kc] + g_bnshift[kc];
                sA[(c4 + q) * SAS + r] = f2tf32(f);
            }
        }
        __syncthreads();

        #pragma unroll
        for (int kk = 0; kk < 32; kk += 8) {
            uint32_t af[2][4], bf[4][2];
            #pragma unroll
            for (int mt = 0; mt < 2; mt++) {
                int mb = mw + mt * 16 + g;
                af[mt][0] = sA[(kk + c) * SAS + mb];
                af[mt][1] = sA[(kk + c) * SAS + mb + 8];
                af[mt][2] = sA[(kk + c + 4) * SAS + mb];
                af[mt][3] = sA[(kk + c + 4) * SAS + mb + 8];
            }
            #pragma unroll
            for (int nt = 0; nt < 4; nt++) {
                int nb = nw + nt * 8 + g;
                bf[nt][0] = sBT[nb * K4 + k0 + kk + c];
                bf[nt][1] = sBT[nb * K4 + k0 + kk + c + 4];
            }
            #pragma unroll
            for (int mt = 0; mt < 2; mt++)
                #pragma unroll
                for (int nt = 0; nt < 4; nt++) {
                    float* cc = acc[mt][nt];
                    asm volatile(
                        "mma.sync.aligned.m16n8k8.row.col.f32.tf32.tf32.f32 "
                        "{%0,%1,%2,%3}, {%4,%5,%6,%7}, {%8,%9}, {%0,%1,%2,%3};"
                        : "+f"(cc[0]), "+f"(cc[1]), "+f"(cc[2]), "+f"(cc[3])
                        : "r"(af[mt][0]), "r"(af[mt][1]), "r"(af[mt][2]), "r"(af[mt][3]),
                          "r"(bf[nt][0]), "r"(bf[nt][1]));
                }
        }
        __syncthreads();
    }

    #pragma unroll
    for (int mt = 0; mt < 2; mt++) {
        #pragma unroll
        for (int nt = 0; nt < 4; nt++) {
            int row = row0 + mw + mt * 16 + g;
            int col = col0 + nw + nt * 8 + 2 * c;
            float* cc = acc[mt][nt];
            if (row < M) {
                if (col < N)     Cg[(size_t)row * ldC + col]     = cc[0];
                if (col + 1 < N) Cg[(size_t)row * ldC + col + 1] = cc[1];
            }
            if (row + 8 < M) {
                if (col < N)     Cg[(size_t)(row + 8) * ldC + col]     = cc[2];
                if (col + 1 < N) Cg[(size_t)(row + 8) * ldC + col + 1] = cc[3];
            }
        }
    }
}

// ---------------- fused GAT layers (warp per node, float2, 2-edge unroll) ----------------
// lane covers dims {64j+2*lane, 64j+2*lane+1} for head j=0..2

__device__ __forceinline__ void gat_upd(float P, float& m, float& z, float2& a, float2 x) {
    if (P > m) {
        float sc = __expf(m - P);
        z = z * sc + 1.f;
        a.x = a.x * sc + x.x;
        a.y = a.y * sc + x.y;
        m = P;
    } else {
        float w = __expf(P - m);
        z += w;
        a.x += x.x * w;
        a.y += x.y * w;
    }
}

__device__ __forceinline__ void gat_core192(int n, int lane, const float* __restrict__ att,
                                            float2 (&acc)[3], float (&z)[3]) {
    const float2* prow = reinterpret_cast<const float2*>(g_xr + (size_t)n * HD192);
    const float2* patt = reinterpret_cast<const float2*>(att);
    float2 attr[3], xrr[3];
    float m[3];
    #pragma unroll
    for (int j = 0; j < 3; j++) {
        attr[j] = patt[32 * j + lane];
        xrr[j]  = prow[32 * j + lane];
        acc[j] = make_float2(0.f, 0.f);
        m[j] = -INFINITY; z[j] = 0.f;
    }
    int e  = g_rowptr[n];
    int e1 = g_rowptr[n + 1];

    for (; e + 2 <= e1; e += 2) {
        int s0 = g_col[e], s1 = g_col[e + 1];
        const float2* pa = reinterpret_cast<const float2*>(g_xl + (size_t)s0 * HD192);
        const float2* pb = reinterpret_cast<const float2*>(g_xl + (size_t)s1 * HD192);
        float2 xa[3], xb[3];
        #pragma unroll
        for (int j = 0; j < 3; j++) { xa[j] = pa[32 * j + lane]; xb[j] = pb[32 * j + lane]; }
        float p[3], q[3];
        #pragma unroll
        for (int j = 0; j < 3; j++) {
            float vx = xa[j].x + xrr[j].x; vx = (vx > 0.f) ? vx : 0.2f * vx;
            float vy = xa[j].y + xrr[j].y; vy = (vy > 0.f) ? vy : 0.2f * vy;
            p[j] = attr[j].x * vx + attr[j].y * vy;
            float wx = xb[j].x + xrr[j].x; wx = (wx > 0.f) ? wx : 0.2f * wx;
            float wy = xb[j].y + xrr[j].y; wy = (wy > 0.f) ? wy : 0.2f * wy;
            q[j] = attr[j].x * wx + attr[j].y * wy;
        }
        #pragma unroll
        for (int o = 16; o > 0; o >>= 1) {
            #pragma unroll
            for (int j = 0; j < 3; j++) {
                p[j] += __shfl_xor_sync(0xffffffffu, p[j], o);
                q[j] += __shfl_xor_sync(0xffffffffu, q[j], o);
            }
        }
        #pragma unroll
        for (int j = 0; j < 3; j++) {
            gat_upd(p[j], m[j], z[j], acc[j], xa[j]);
            gat_upd(q[j], m[j], z[j], acc[j], xb[j]);
        }
    }
    if (e < e1) {
        int s0 = g_col[e];
        const float2* pa = reinterpret_cast<const float2*>(g_xl + (size_t)s0 * HD192);
        float2 xa[3];
        #pragma unroll
        for (int j = 0; j < 3; j++) xa[j] = pa[32 * j + lane];
        float p[3];
        #pragma unroll
        for (int j = 0; j < 3; j++) {
            float vx = xa[j].x + xrr[j].x; vx = (vx > 0.f) ? vx : 0.2f * vx;
            float vy = xa[j].y + xrr[j].y; vy = (vy > 0.f) ? vy : 0.2f * vy;
            p[j] = attr[j].x * vx + attr[j].y * vy;
        }
        #pragma unroll
        for (int o = 16; o > 0; o >>= 1)
            #pragma unroll
            for (int j = 0; j < 3; j++)
                p[j] += __shfl_xor_sync(0xffffffffu, p[j], o);
        #pragma unroll
        for (int j = 0; j < 3; j++)
            gat_upd(p[j], m[j], z[j], acc[j], xa[j]);
    }
}

__global__ void gat1_kernel(const float* __restrict__ att, const float* __restrict__ b1) {
    __shared__ float sbn[HD192], sbq[HD192];
    int tid = threadIdx.x;
    if (tid < HD192) { sbn[tid] = 0.f; sbq[tid] = 0.f; }
    __syncthreads();
    int lane = tid & 31, wib = tid >> 5;
    int n = blockIdx.x * 8 + wib;
    if (n < NN) {
        float2 acc[3]; float z[3];
        gat_core192(n, lane, att, acc, z);
        float2* ph = reinterpret_cast<float2*>(g_h + (size_t)n * HD192);
        const float2* pb = reinterpret_cast<const float2*>(b1);
        #pragma unroll
        for (int j = 0; j < 3; j++) {
            float iz = 1.f / z[j];
            float2 b = pb[32 * j + lane];
            float ox = fmaxf(acc[j].x * iz + b.x, 0.f);
            float oy = fmaxf(acc[j].y * iz + b.y, 0.f);
            ph[32 * j + lane] = make_float2(ox, oy);
            int c = 64 * j + 2 * lane;
            atomicAdd(&sbn[c],     ox);
            atomicAdd(&sbn[c + 1], oy);
            atomicAdd(&sbq[c],     ox * ox);
            atomicAdd(&sbq[c + 1], oy * oy);
        }
    }
    __syncthreads();
    if (tid < HD192) {
        atomicAdd(&g_bnsum[tid], sbn[tid]);
        atomicAdd(&g_bnsq[tid], sbq[tid]);
    }
}

__global__ void bn_prep_kernel(const float* __restrict__ gamma, const float* __restrict__ beta) {
    int c = threadIdx.x;
    if (c < HD192) {
        float mu = g_bnsum[c] * (1.f / NN);
        float var = g_bnsq[c] * (1.f / NN) - mu * mu;
        float s = gamma[c] * rsqrtf(var + EPSBN);
        g_bnscale[c] = s;
        g_bnshift[c] = beta[c] - mu * s;
    }
}

__global__ void gat2_kernel(const float* __restrict__ att, const float* __restrict__ b2,
                            const int* __restrict__ batch) {
    int tid = threadIdx.x;
    int lane = tid & 31, wib = tid >> 5;
    int n = blockIdx.x * 8 + wib;
    if (n >= NN) return;
    float2 acc[3]; float z[3];
    gat_core192(n, lane, att, acc, z);
    float iz0 = 1.f / z[0], iz1 = 1.f / z[1], iz2 = 1.f / z[2];
    const float2* pb = reinterpret_cast<const float2*>(b2);
    float2 b = pb[lane];
    float2 v;
    v.x = (acc[0].x * iz0 + acc[1].x * iz1 + acc[2].x * iz2) * (1.f / 3.f) + b.x;
    v.y = (acc[0].y * iz0 + acc[1].y * iz1 + acc[2].y * iz2) * (1.f / 3.f) + b.y;
    reinterpret_cast<float2*>(g_h2 + (size_t)n * D64)[lane] = v;
    int bt = batch[n];
    atomicAdd(&g_pool[bt * D64 + 2 * lane],     v.x);
    atomicAdd(&g_pool[bt * D64 + 2 * lane + 1], v.y);
    if (lane == 0) atomicAdd(&g_cnt[bt], 1.f);
}

// layer 3: rows stored with stride 64 (col 63 is GEMM pad, masked to 0 here)
__global__ void gat3_kernel(const float* __restrict__ att, const float* __restrict__ b3,
                            float* __restrict__ out) {
    __shared__ float sh[8][64];
    int tid = threadIdx.x;
    int lane = tid & 31, wib = tid >> 5;
    int n = blockIdx.x * 8 + wib;
    if (n >= NN) return;
    int d0 = 2 * lane, d1 = d0 + 1;
    bool ok1 = (d1 < HD63);
    int h0 = d0 / D21;
    int h1 = ok1 ? (d1 / D21) : 2;
    float at0 = att[d0];
    float at1 = ok1 ? att[d1] : 0.f;
    float2 xr2 = reinterpret_cast<const float2*>(g_xr + (size_t)n * D64)[lane];
    if (!ok1) xr2.y = 0.f;
    float2 a = make_float2(0.f, 0.f);
    float m[3] = {-INFINITY, -INFINITY, -INFINITY};
    float z[3] = {0.f, 0.f, 0.f};
    int e  = g_rowptr[n];
    int e1 = g_rowptr[n + 1];
    for (; e + 2 <= e1; e += 2) {
        int s0 = g_col[e], s1 = g_col[e + 1];
        float2 xa = reinterpret_cast<const float2*>(g_xl + (size_t)s0 * D64)[lane];
        float2 xb = reinterpret_cast<const float2*>(g_xl + (size_t)s1 * D64)[lane];
        if (!ok1) { xa.y = 0.f; xb.y = 0.f; }
        float tax = xa.x + xr2.x; tax = (tax > 0.f) ? tax : 0.2f * tax;
        float tay = xa.y + xr2.y; tay = (tay > 0.f) ? tay : 0.2f * tay;
        float tbx = xb.x + xr2.x; tbx = (tbx > 0.f) ? tbx : 0.2f * tbx;
        float tby = xb.y + xr2.y; tby = (tby > 0.f) ? tby : 0.2f * tby;
        float qa0 = at0 * tax, qa1 = at1 * tay;
        float qb0 = at0 * tbx, qb1 = at1 * tby;
        float p[3], q[3];
        #pragma unroll
        for (int j = 0; j < 3; j++) {
            p[j] = ((h0 == j) ? qa0 : 0.f) + ((h1 == j && ok1) ? qa1 : 0.f);
            q[j] = ((h0 == j) ? qb0 : 0.f) + ((h1 == j && ok1) ? qb1 : 0.f);
        }
        #pragma unroll
        for (int o = 16; o > 0; o >>= 1) {
            #pragma unroll
            for (int j = 0; j < 3; j++) {
                p[j] += __shfl_xor_sync(0xffffffffu, p[j], o);
                q[j] += __shfl_xor_sync(0xffffffffu, q[j], o);
            }
        }
        float sc[3], wt[3];
        #pragma unroll
        for (int j = 0; j < 3; j++) {
            if (p[j] > m[j]) { sc[j] = __expf(m[j] - p[j]); wt[j] = 1.f; z[j] = z[j] * sc[j] + 1.f; m[j] = p[j]; }
            else             { sc[j] = 1.f; wt[j] = __expf(p[j] - m[j]); z[j] += wt[j]; }
        }
        a.x = a.x * sc[h0] + xa.x * wt[h0];
        a.y = a.y * sc[h1] + xa.y * wt[h1];
        #pragma unroll
        for (int j = 0; j < 3; j++) {
            if (q[j] > m[j]) { sc[j] = __expf(m[j] - q[j]); wt[j] = 1.f; z[j] = z[j] * sc[j] + 1.f; m[j] = q[j]; }
            else             { sc[j] = 1.f; wt[j] = __expf(q[j] - m[j]); z[j] += wt[j]; }
        }
        a.x = a.x * sc[h0] + xb.x * wt[h0];
        a.y = a.y * sc[h1] + xb.y * wt[h1];
    }
    if (e < e1) {
        int s0 = g_col[e];
        float2 xa = reinterpret_cast<const float2*>(g_xl + (size_t)s0 * D64)[lane];
        if (!ok1) xa.y = 0.f;
        float tax = xa.x + xr2.x; tax = (tax > 0.f) ? tax : 0.2f * tax;
        float tay = xa.y + xr2.y; tay = (tay > 0.f) ? tay : 0.2f * tay;
        float qa0 = at0 * tax, qa1 = at1 * tay;
        float p[3];
        #pragma unroll
        for (int j = 0; j < 3; j++)
            p[j] = ((h0 == j) ? qa0 : 0.f) + ((h1 == j && ok1) ? qa1 : 0.f);
        #pragma unroll
        for (int o = 16; o > 0; o >>= 1)
            #pragma unroll
            for (int j = 0; j < 3; j++)
                p[j] += __shfl_xor_sync(0xffffffffu, p[j], o);
        float sc[3], wt[3];
        #pragma unroll
        for (int j = 0; j < 3; j++) {
            if (p[j] > m[j]) { sc[j] = __expf(m[j] - p[j]); wt[j] = 1.f; z[j] = z[j] * sc[j] + 1.f; m[j] = p[j]; }
            else             { sc[j] = 1.f; wt[j] = __expf(p[j] - m[j]); z[j] += wt[j]; }
        }
        a.x = a.x * sc[h0] + xa.x * wt[h0];
        a.y = a.y * sc[h1] + xa.y * wt[h1];
    }
    sh[wib][d0] = a.x / z[h0];
    if (ok1) sh[wib][d1] = a.y / z[h1];
    __syncwarp();
    if (lane < D21) {
        float o = (sh[wib][lane] + sh[wib][lane + D21] + sh[wib][lane + 2 * D21]) * (1.f / 3.f)
                  + b3[lane];
        out[NG * NCLS + (size_t)n * D21 + lane] = o;
    }
}

__global__ void classifier_kernel(const float* __restrict__ Wc, const float* __restrict__ bc,
                                  float* __restrict__ out) {
    int t = threadIdx.x;
    if (t >= NG * NCLS) return;
    int g = t / NCLS, j = t % NCLS;
    float cnt = fmaxf(g_cnt[g], 1.f);
    float s = bc[j];
    #pragma unroll
    for (int d = 0; d < D64; d++)
        s += (g_pool[g * D64 + d] / cnt) * Wc[d * NCLS + j];
    out[t] = s;
}

// ---------------- launch ----------------
extern "C" void kernel_launch(void* const* d_in, const int* in_sizes, int n_in,
                              void* d_out, int out_size) {
    const float* x     = (const float*)d_in[0];
    const int*   ei    = (const int*)d_in[1];
    const int*   batch = (const int*)d_in[2];
    const float* Wl1   = (const float*)d_in[3];
    const float* Wr1   = (const float*)d_in[4];
    const float* att1  = (const float*)d_in[5];
    const float* b1    = (const float*)d_in[6];
    const float* gamma = (const float*)d_in[7];
    const float* beta  = (const float*)d_in[8];
    const float* Wl2   = (const float*)d_in[9];
    const float* Wr2   = (const float*)d_in[10];
    const float* att2  = (const float*)d_in[11];
    const float* b2    = (const float*)d_in[12];
    const float* Wl3   = (const float*)d_in[13];
    const float* Wr3   = (const float*)d_in[14];
    const float* att3  = (const float*)d_in[15];
    const float* b3    = (const float*)d_in[16];
    const float* Wc    = (const float*)d_in[17];
    const float* bc    = (const float*)d_in[18];
    float* out = (float*)d_out;

    const int* src  = ei;
    const int* dstp = ei + NE;

    float *pxl, *pxr, *ph, *ph2;
    cudaGetSymbolAddress((void**)&pxl, g_xl);
    cudaGetSymbolAddress((void**)&pxr, g_xr);
    cudaGetSymbolAddress((void**)&ph,  g_h);
    cudaGetSymbolAddress((void**)&ph2, g_h2);

    auto smem_for = [](int K) { return (size_t)(64 * (K + 4) + 32 * SAS) * 4; };

    static bool inited = false;
    static cudaStream_t s2 = nullptr;
    static cudaEvent_t evA = nullptr, evB = nullptr, evC = nullptr, evD = nullptr;
    if (!inited) {
        cudaFuncSetAttribute(gemm_tf32_kernel,
                             cudaFuncAttributeMaxDynamicSharedMemorySize,
                             (int)smem_for(HD192));
        if (cudaStreamCreateWithFlags(&s2, cudaStreamNonBlocking) != cudaSuccess) s2 = nullptr;
        if (s2) {
            bool ok = true;
            ok &= (cudaEventCreateWithFlags(&evA, cudaEventDisableTiming) == cudaSuccess);
            ok &= (cudaEventCreateWithFlags(&evB, cudaEventDisableTiming) == cudaSuccess);
            ok &= (cudaEventCreateWithFlags(&evC, cudaEventDisableTiming) == cudaSuccess);
            ok &= (cudaEventCreateWithFlags(&evD, cudaEventDisableTiming) == cudaSuccess);
            if (!ok) s2 = nullptr;
        }
        inited = true;
    }
    cudaStream_t sc = s2 ? s2 : (cudaStream_t)0;   // CSR/classifier stream

    const int gat_grid = (NN + 7) / 8;
    const int my = (NN + 127) / 128;

    // fork: CSR build (+small resets) runs concurrent with layer-1 GEMM
    if (s2) { cudaEventRecord(evA, 0); cudaStreamWaitEvent(s2, evA, 0); }
    reset_small_kernel<<<1, 512, 0, sc>>>();
    init_counts_kernel<<<(NN + 255) / 256, 256, 0, sc>>>();
    hist_kernel<<<(NE + 255) / 256, 256, 0, sc>>>(dstp);
    scan1_kernel<<<SBLK, 256, 0, sc>>>();
    scan2_kernel<<<1, 128, 0, sc>>>();
    scan3_kernel<<<SBLK, 256, 0, sc>>>();
    csr_fill_kernel<<<(ETOT + 255) / 256, 256, 0, sc>>>(src, dstp);
    if (s2) cudaEventRecord(evB, s2);

    // ---- layer 1: x(128) -> 3x64 concat ----
    {
        dim3 g(3, my, 2);
        gemm_tf32_kernel<<<g, 256, smem_for(128)>>>(x, Wl1, Wr1, pxl, pxr, NN, HD192, 128, HD192, 0);
    }
    if (s2) cudaStreamWaitEvent(0, evB, 0);   // join CSR before gat1
    gat1_kernel<<<gat_grid, 256>>>(att1, b1);
    bn_prep_kernel<<<1, 256>>>(gamma, beta);

    // ---- layer 2: BN(h)(192) -> 64 (head mean), + pooling ----
    {
        dim3 g(3, my, 2);
        gemm_tf32_kernel<<<g, 256, smem_for(HD192)>>>(ph, Wl2, Wr2, pxl, pxr, NN, HD192, HD192, HD192, 2);
    }
    gat2_kernel<<<gat_grid, 256>>>(att2, b2, batch);

    // classifier overlaps layer-3 GEMM
    if (s2) { cudaEventRecord(evC, 0); cudaStreamWaitEvent(s2, evC, 0); }
    classifier_kernel<<<1, 128, 0, sc>>>(Wc, bc, out);
    if (s2) cudaEventRecord(evD, s2);

    // ---- layer 3: relu(h2)(64) -> 21 (head mean), rows padded to stride 64 ----
    {
        dim3 g(1, my, 2);
        gemm_tf32_kernel<<<g, 256, smem_for(D64)>>>(ph2, Wl3, Wr3, pxl, pxr, NN, HD63, D64, D64, 1);
    }
    gat3_kernel<<<gat_grid, 256>>>(att3, b3, out);
    if (s2) cudaStreamWaitEvent(0, evD, 0);   // rejoin before capture ends
}